// round 1
// baseline (speedup 1.0000x reference)
#include <cuda_runtime.h>
#include <cuda_bf16.h>
#include <cstdint>

// Problem constants
#define NNODES 100000
#define NEDGES 1600000
#define DIN 128
#define DH 128
#define DOUT 64

// ---------------- scratch (device globals; no allocation allowed) -------------
__device__ int   g_deg[NNODES];          // in-degree + 1 (self loop)
__device__ float g_dinv[NNODES];         // rsqrt(deg)
__device__ int   g_off[NNODES];          // CSR offsets (exclusive scan of in-degree)
__device__ int   g_cursor[NNODES];       // scatter cursors
__device__ int   g_csr_src[NEDGES];      // CSR column (src node)
__device__ float g_csr_w[NEDGES];        // precomputed dinv[s]*dinv[d]
__device__ float g_bufA[(size_t)NNODES * DIN];
__device__ float g_bufB[(size_t)NNODES * DIN];

#define SCAN_CHUNK 1024
#define SCAN_BLOCKS 98               // ceil(100000/1024)
__device__ int g_bsum[SCAN_BLOCKS];

// ---------------- CSR build ---------------------------------------------------
__global__ void k_init(void) {
    int v = blockIdx.x * blockDim.x + threadIdx.x;
    if (v < NNODES) { g_deg[v] = 1; g_cursor[v] = 0; }
}

__global__ void k_count(const int* __restrict__ dst) {
    int e = blockIdx.x * blockDim.x + threadIdx.x;
    if (e < NEDGES) atomicAdd(&g_deg[dst[e]], 1);
}

__global__ void k_dinv(void) {
    int v = blockIdx.x * blockDim.x + threadIdx.x;
    if (v < NNODES) g_dinv[v] = rsqrtf((float)g_deg[v]);
}

// exclusive scan of (deg-1) : 3 phases
__global__ void k_scan_block(void) {
    __shared__ int wsum[8];
    int tid = threadIdx.x;
    int base = blockIdx.x * SCAN_CHUNK + tid * 4;
    int v[4];
#pragma unroll
    for (int i = 0; i < 4; i++) {
        int idx = base + i;
        v[i] = (idx < NNODES) ? (g_deg[idx] - 1) : 0;
    }
    int e0 = 0, e1 = v[0], e2 = v[0] + v[1], e3 = v[0] + v[1] + v[2];
    int tot = e3 + v[3];
    // warp inclusive scan of tot
    int lane = tid & 31, wid = tid >> 5;
    int x = tot;
#pragma unroll
    for (int off = 1; off < 32; off <<= 1) {
        int y = __shfl_up_sync(0xFFFFFFFFu, x, off);
        if (lane >= off) x += y;
    }
    if (lane == 31) wsum[wid] = x;
    __syncthreads();
    if (wid == 0) {
        int t = (lane < 8) ? wsum[lane] : 0;
        int xx = t;
#pragma unroll
        for (int off = 1; off < 8; off <<= 1) {
            int y = __shfl_up_sync(0xFFFFFFFFu, xx, off);
            if (lane >= off) xx += y;
        }
        if (lane < 8) wsum[lane] = xx - t;   // exclusive
    }
    __syncthreads();
    int texc = wsum[wid] + (x - tot);        // exclusive offset of this thread in block
    int o0 = texc + e0, o1 = texc + e1, o2 = texc + e2, o3 = texc + e3;
    if (base + 0 < NNODES) g_off[base + 0] = o0;
    if (base + 1 < NNODES) g_off[base + 1] = o1;
    if (base + 2 < NNODES) g_off[base + 2] = o2;
    if (base + 3 < NNODES) g_off[base + 3] = o3;
    if (tid == blockDim.x - 1) g_bsum[blockIdx.x] = texc + tot;
}

__global__ void k_scan_top(void) {
    int acc = 0;
    for (int b = 0; b < SCAN_BLOCKS; b++) {
        int t = g_bsum[b];
        g_bsum[b] = acc;
        acc += t;
    }
}

__global__ void k_scan_add(void) {
    int tid = threadIdx.x;
    int base = blockIdx.x * SCAN_CHUNK + tid * 4;
    int add = g_bsum[blockIdx.x];
#pragma unroll
    for (int i = 0; i < 4; i++) {
        int idx = base + i;
        if (idx < NNODES) g_off[idx] += add;
    }
}

__global__ void k_scatter(const int* __restrict__ src, const int* __restrict__ dst) {
    int e = blockIdx.x * blockDim.x + threadIdx.x;
    if (e >= NEDGES) return;
    int s = src[e], d = dst[e];
    int pos = g_off[d] + atomicAdd(&g_cursor[d], 1);
    g_csr_src[pos] = s;
    g_csr_w[pos] = g_dinv[s] * g_dinv[d];
}

// ---------------- SGEMM: C[M,BN] = A[M,128] @ B[128,BN] ----------------------
template <int BN>
__global__ __launch_bounds__(256) void k_sgemm(const float* __restrict__ A,
                                               const float* __restrict__ B,
                                               float* __restrict__ C, int M) {
    constexpr int BM = 128, BK = 8, TM = 8, TN = BN / 16;
    __shared__ float As[BK][BM + 4];   // pitch 132: conflict-free frag loads
    __shared__ float Bs[BK][BN];

    int tid = threadIdx.x;
    int ty = tid / 16, tx = tid % 16;
    int blockRow = blockIdx.x * BM;

    float acc[TM][TN];
#pragma unroll
    for (int i = 0; i < TM; i++)
#pragma unroll
        for (int j = 0; j < TN; j++) acc[i][j] = 0.0f;

    int arow = tid >> 1;
    int acol = (tid & 1) * 4;
    int brow = tid / (BN / 4);
    int bcol = (tid % (BN / 4)) * 4;

    for (int k0 = 0; k0 < 128; k0 += BK) {
        float4 a = make_float4(0.f, 0.f, 0.f, 0.f);
        if (blockRow + arow < M)
            a = *reinterpret_cast<const float4*>(&A[(size_t)(blockRow + arow) * 128 + k0 + acol]);
        As[acol + 0][arow] = a.x;
        As[acol + 1][arow] = a.y;
        As[acol + 2][arow] = a.z;
        As[acol + 3][arow] = a.w;

        if (BN == 128 || tid < 128) {
            float4 b = *reinterpret_cast<const float4*>(&B[(size_t)(k0 + brow) * BN + bcol]);
            *reinterpret_cast<float4*>(&Bs[brow][bcol]) = b;
        }
        __syncthreads();

#pragma unroll
        for (int kk = 0; kk < BK; kk++) {
            float ar[TM], br[TN];
            const float4* ap = reinterpret_cast<const float4*>(&As[kk][ty * TM]);
            float4 a0 = ap[0], a1 = ap[1];
            ar[0] = a0.x; ar[1] = a0.y; ar[2] = a0.z; ar[3] = a0.w;
            ar[4] = a1.x; ar[5] = a1.y; ar[6] = a1.z; ar[7] = a1.w;
            const float4* bp = reinterpret_cast<const float4*>(&Bs[kk][tx * TN]);
#pragma unroll
            for (int j4 = 0; j4 < TN / 4; j4++) {
                float4 b4 = bp[j4];
                br[j4 * 4 + 0] = b4.x; br[j4 * 4 + 1] = b4.y;
                br[j4 * 4 + 2] = b4.z; br[j4 * 4 + 3] = b4.w;
            }
#pragma unroll
            for (int i = 0; i < TM; i++)
#pragma unroll
                for (int j = 0; j < TN; j++) acc[i][j] += ar[i] * br[j];
        }
        __syncthreads();
    }

#pragma unroll
    for (int i = 0; i < TM; i++) {
        int row = blockRow + ty * TM + i;
        if (row >= M) continue;
#pragma unroll
        for (int j4 = 0; j4 < TN / 4; j4++) {
            float4 o;
            o.x = acc[i][j4 * 4 + 0]; o.y = acc[i][j4 * 4 + 1];
            o.z = acc[i][j4 * 4 + 2]; o.w = acc[i][j4 * 4 + 3];
            *reinterpret_cast<float4*>(&C[(size_t)row * BN + tx * TN + j4 * 4]) = o;
        }
    }
}

// ---------------- Aggregation: out[v] = sum_{(s,v)} w * h[s] (+self) + bias ---
// one warp per dst node, lane covers DIM/32 contiguous features
template <int DIM, bool RELU>
__global__ __launch_bounds__(256) void k_agg(const float* __restrict__ h,
                                             const float* __restrict__ bias,
                                             float* __restrict__ out) {
    int warp = (blockIdx.x * blockDim.x + threadIdx.x) >> 5;
    if (warp >= NNODES) return;
    int lane = threadIdx.x & 31;

    float dv = g_dinv[warp];
    float wself = dv * dv;
    int beg = g_off[warp];
    int end = beg + (g_deg[warp] - 1);

    if (DIM == 128) {
        const float4* hp = reinterpret_cast<const float4*>(h);
        float4 sv = hp[(size_t)warp * 32 + lane];
        float ax = sv.x * wself, ay = sv.y * wself, az = sv.z * wself, aw = sv.w * wself;
        int e = beg;
        for (; e + 1 < end; e += 2) {
            int s0 = g_csr_src[e], s1 = g_csr_src[e + 1];
            float w0 = g_csr_w[e], w1 = g_csr_w[e + 1];
            float4 v0 = hp[(size_t)s0 * 32 + lane];
            float4 v1 = hp[(size_t)s1 * 32 + lane];
            ax += v0.x * w0 + v1.x * w1;
            ay += v0.y * w0 + v1.y * w1;
            az += v0.z * w0 + v1.z * w1;
            aw += v0.w * w0 + v1.w * w1;
        }
        if (e < end) {
            int s0 = g_csr_src[e];
            float w0 = g_csr_w[e];
            float4 v0 = hp[(size_t)s0 * 32 + lane];
            ax += v0.x * w0; ay += v0.y * w0; az += v0.z * w0; aw += v0.w * w0;
        }
        float4 b4 = reinterpret_cast<const float4*>(bias)[lane];
        ax += b4.x; ay += b4.y; az += b4.z; aw += b4.w;
        if (RELU) {
            ax = fmaxf(ax, 0.f); ay = fmaxf(ay, 0.f);
            az = fmaxf(az, 0.f); aw = fmaxf(aw, 0.f);
        }
        float4 o; o.x = ax; o.y = ay; o.z = az; o.w = aw;
        reinterpret_cast<float4*>(out)[(size_t)warp * 32 + lane] = o;
    } else {  // DIM == 64
        const float2* hp = reinterpret_cast<const float2*>(h);
        float2 sv = hp[(size_t)warp * 32 + lane];
        float ax = sv.x * wself, ay = sv.y * wself;
        int e = beg;
        for (; e + 1 < end; e += 2) {
            int s0 = g_csr_src[e], s1 = g_csr_src[e + 1];
            float w0 = g_csr_w[e], w1 = g_csr_w[e + 1];
            float2 v0 = hp[(size_t)s0 * 32 + lane];
            float2 v1 = hp[(size_t)s1 * 32 + lane];
            ax += v0.x * w0 + v1.x * w1;
            ay += v0.y * w0 + v1.y * w1;
        }
        if (e < end) {
            int s0 = g_csr_src[e];
            float w0 = g_csr_w[e];
            float2 v0 = hp[(size_t)s0 * 32 + lane];
            ax += v0.x * w0; ay += v0.y * w0;
        }
        float2 b2 = reinterpret_cast<const float2*>(bias)[lane];
        ax += b2.x; ay += b2.y;
        if (RELU) { ax = fmaxf(ax, 0.f); ay = fmaxf(ay, 0.f); }
        float2 o; o.x = ax; o.y = ay;
        reinterpret_cast<float2*>(out)[(size_t)warp * 32 + lane] = o;
    }
}

// ---------------- launch ------------------------------------------------------
extern "C" void kernel_launch(void* const* d_in, const int* in_sizes, int n_in,
                              void* d_out, int out_size) {
    const float* x  = (const float*)d_in[0];
    const int*   ei = (const int*)d_in[1];
    const float* W1 = (const float*)d_in[2];
    const float* b1 = (const float*)d_in[3];
    const float* W2 = (const float*)d_in[4];
    const float* b2 = (const float*)d_in[5];
    const float* W3 = (const float*)d_in[6];
    const float* b3 = (const float*)d_in[7];
    float* out = (float*)d_out;

    const int* src = ei;
    const int* dst = ei + NEDGES;

    float* bufA; cudaGetSymbolAddress((void**)&bufA, g_bufA);
    float* bufB; cudaGetSymbolAddress((void**)&bufB, g_bufB);

    const int TB = 256;
    int nodeBlocks = (NNODES + TB - 1) / TB;   // 391
    int edgeBlocks = (NEDGES + TB - 1) / TB;   // 6250
    int gemmBlocks = (NNODES + 127) / 128;     // 782
    int aggBlocks  = (NNODES + 7) / 8;         // 12500 (8 warps/block)

    // graph preprocessing (shared across layers)
    k_init<<<nodeBlocks, TB>>>();
    k_count<<<edgeBlocks, TB>>>(dst);
    k_dinv<<<nodeBlocks, TB>>>();
    k_scan_block<<<SCAN_BLOCKS, TB>>>();
    k_scan_top<<<1, 1>>>();
    k_scan_add<<<SCAN_BLOCKS, TB>>>();
    k_scatter<<<edgeBlocks, TB>>>(src, dst);

    // layer 1: agg(x@W1)+b1 -> relu
    k_sgemm<128><<<gemmBlocks, TB>>>(x, W1, bufA, NNODES);
    k_agg<128, true><<<aggBlocks, TB>>>(bufA, b1, bufB);
    // layer 2
    k_sgemm<128><<<gemmBlocks, TB>>>(bufB, W2, bufA, NNODES);
    k_agg<128, true><<<aggBlocks, TB>>>(bufA, b2, bufB);
    // layer 3 (transform first: 64-dim aggregation)
    k_sgemm<64><<<gemmBlocks, TB>>>(bufB, W3, bufA, NNODES);
    k_agg<64, false><<<aggBlocks, TB>>>(bufA, b3, out);
}